// round 7
// baseline (speedup 1.0000x reference)
#include <cuda_runtime.h>
#include <cstdint>
#include <cstddef>

// Problem constants (fixed by the dataset)
#define N_TOK   1048576
#define B_SEG   4096
#define D_IN    256
#define H_MLP   128
#define N_TILES (N_TOK / 16)      // 65536 tiles of 16 tokens

// smem: 16 kt * 16 nt * 32 lanes * 16B packed W1 fragments + 128 float2 (b1,W2)
#define BFRAG_ELEMS (16 * 16 * 32)
#define SMEM_BYTES  (BFRAG_ELEMS * 16 + H_MLP * 8)

__device__ int g_start[B_SEG + 1];

// ---------------------------------------------------------------------------
// helpers
// ---------------------------------------------------------------------------
__device__ __forceinline__ uint32_t pack_bf16x2(float hi, float lo) {
    // result = { upper16 = bf16(hi), lower16 = bf16(lo) }
    uint32_t r;
    asm("cvt.rn.bf16x2.f32 %0, %1, %2;" : "=r"(r) : "f"(hi), "f"(lo));
    return r;
}

__device__ __forceinline__ void mma_bf16(float d[4],
                                         uint32_t a0, uint32_t a1, uint32_t a2, uint32_t a3,
                                         uint32_t b0, uint32_t b1) {
    asm volatile(
        "mma.sync.aligned.m16n8k16.row.col.f32.bf16.bf16.f32 "
        "{%0,%1,%2,%3}, {%4,%5,%6,%7}, {%8,%9}, {%0,%1,%2,%3};\n"
        : "+f"(d[0]), "+f"(d[1]), "+f"(d[2]), "+f"(d[3])
        : "r"(a0), "r"(a1), "r"(a2), "r"(a3), "r"(b0), "r"(b1));
}

__device__ __forceinline__ float fast_tanh(float v) {
    // tanh(v) = 1 - 2/(exp(2v)+1); saturates correctly at +/-inf of the exp.
    float e = __expf(2.0f * v);
    return 1.0f - __fdividef(2.0f, e + 1.0f);
}

// ---------------------------------------------------------------------------
// Pass 0: segment start offsets via binary search (ids are sorted)
// ---------------------------------------------------------------------------
__global__ void find_starts_kernel(const int* __restrict__ seg) {
    int b = blockIdx.x * blockDim.x + threadIdx.x;
    if (b > B_SEG) return;
    if (b == B_SEG) { g_start[B_SEG] = N_TOK; return; }
    int lo = 0, hi = N_TOK;
    while (lo < hi) {
        int mid = (lo + hi) >> 1;
        if (seg[mid] < b) lo = mid + 1; else hi = mid;
    }
    g_start[b] = lo;
}

// ---------------------------------------------------------------------------
// Pass 1: s[n] = tanh(x @ W1 + b1) @ W2 + b2   via split-bf16 tensor-core GEMM
// One warp computes a 16-token x 128-hidden tile; K=256 in 16 steps.
// W1 fragments (hi+lo bf16 split) pre-packed in smem in mma B-fragment layout.
// ---------------------------------------------------------------------------
__global__ __launch_bounds__(512, 1)
void logits_kernel(const float* __restrict__ x,
                   const float* __restrict__ W1,
                   const float* __restrict__ b1,
                   const float* __restrict__ W2,
                   const float* __restrict__ b2,
                   float* __restrict__ s_out) {
    extern __shared__ unsigned char smem_raw[];
    uint4*  bfrag = reinterpret_cast<uint4*>(smem_raw);
    float2* pw    = reinterpret_cast<float2*>(smem_raw + BFRAG_ELEMS * 16);

    const int tid = threadIdx.x;

    // --- pack W1 (hi/lo bf16 split) into B-fragment layout ---
    for (int e = tid; e < BFRAG_ELEMS; e += 512) {
        int kt = e >> 9;
        int nt = (e >> 5) & 15;
        int ln = e & 31;
        int k0 = kt * 16 + (ln & 3) * 2;      // k index of b0
        int nn = nt * 8 + (ln >> 2);          // n index
        float v0 = W1[(k0    ) * H_MLP + nn];
        float v1 = W1[(k0 + 1) * H_MLP + nn];
        float v2 = W1[(k0 + 8) * H_MLP + nn];
        float v3 = W1[(k0 + 9) * H_MLP + nn];
        uint32_t h0 = pack_bf16x2(v1, v0);
        uint32_t h1 = pack_bf16x2(v3, v2);
        float r0 = v0 - __uint_as_float(h0 << 16);
        float r1 = v1 - __uint_as_float(h0 & 0xffff0000u);
        float r2 = v2 - __uint_as_float(h1 << 16);
        float r3 = v3 - __uint_as_float(h1 & 0xffff0000u);
        uint32_t l0 = pack_bf16x2(r1, r0);
        uint32_t l1 = pack_bf16x2(r3, r2);
        bfrag[e] = make_uint4(h0, h1, l0, l1);
    }
    for (int n = tid; n < H_MLP; n += 512)
        pw[n] = make_float2(b1[n], W2[n]);
    const float bias2 = b2[0];
    __syncthreads();

    const int warp  = tid >> 5;
    const int lane  = tid & 31;
    const int g     = lane >> 2;          // row within groups
    const int cbase = (lane & 3) * 2;     // col pair base

    for (int tile = blockIdx.x * 16 + warp; tile < N_TILES; tile += gridDim.x * 16) {
        const float* xr0 = x + (size_t)(tile * 16 + g) * D_IN;
        const float* xr1 = xr0 + 8 * D_IN;

        float acc[64];
#pragma unroll
        for (int i = 0; i < 64; i++) acc[i] = 0.0f;

        // prefetch kt = 0
        float2 q0 = *reinterpret_cast<const float2*>(xr0 + cbase);
        float2 q1 = *reinterpret_cast<const float2*>(xr0 + cbase + 8);
        float2 q2 = *reinterpret_cast<const float2*>(xr1 + cbase);
        float2 q3 = *reinterpret_cast<const float2*>(xr1 + cbase + 8);

#pragma unroll 1
        for (int kt = 0; kt < 16; kt++) {
            float2 c0 = q0, c1 = q1, c2 = q2, c3 = q3;
            if (kt < 15) {
                int c = (kt + 1) * 16 + cbase;
                q0 = *reinterpret_cast<const float2*>(xr0 + c);
                q1 = *reinterpret_cast<const float2*>(xr0 + c + 8);
                q2 = *reinterpret_cast<const float2*>(xr1 + c);
                q3 = *reinterpret_cast<const float2*>(xr1 + c + 8);
            }
            // A fragments: a0=(r0,c..), a1=(r1,c..), a2=(r0,c+8..), a3=(r1,c+8..)
            uint32_t ah0 = pack_bf16x2(c0.y, c0.x);
            uint32_t ah1 = pack_bf16x2(c2.y, c2.x);
            uint32_t ah2 = pack_bf16x2(c1.y, c1.x);
            uint32_t ah3 = pack_bf16x2(c3.y, c3.x);
            uint32_t al0 = pack_bf16x2(c0.y - __uint_as_float(ah0 & 0xffff0000u),
                                       c0.x - __uint_as_float(ah0 << 16));
            uint32_t al1 = pack_bf16x2(c2.y - __uint_as_float(ah1 & 0xffff0000u),
                                       c2.x - __uint_as_float(ah1 << 16));
            uint32_t al2 = pack_bf16x2(c1.y - __uint_as_float(ah2 & 0xffff0000u),
                                       c1.x - __uint_as_float(ah2 << 16));
            uint32_t al3 = pack_bf16x2(c3.y - __uint_as_float(ah3 & 0xffff0000u),
                                       c3.x - __uint_as_float(ah3 << 16));

            const uint4* bp = bfrag + kt * 512 + lane;
#pragma unroll
            for (int nt = 0; nt < 16; nt++) {
                uint4 bb = bp[nt * 32];             // one conflict-free LDS.128
                float* d = &acc[nt * 4];
                mma_bf16(d, ah0, ah1, ah2, ah3, bb.x, bb.y);  // x_hi * W_hi
                mma_bf16(d, al0, al1, al2, al3, bb.x, bb.y);  // x_lo * W_hi
                mma_bf16(d, ah0, ah1, ah2, ah3, bb.z, bb.w);  // x_hi * W_lo
            }
        }

        // epilogue: s = sum_n tanh(h + b1) * W2
        float p0 = 0.0f, p1 = 0.0f;
#pragma unroll
        for (int nt = 0; nt < 16; nt++) {
            int n0 = nt * 8 + cbase;
            float2 w0 = pw[n0];
            float2 w1 = pw[n0 + 1];
            p0 += fast_tanh(acc[nt * 4 + 0] + w0.x) * w0.y;
            p0 += fast_tanh(acc[nt * 4 + 1] + w1.x) * w1.y;
            p1 += fast_tanh(acc[nt * 4 + 2] + w0.x) * w0.y;
            p1 += fast_tanh(acc[nt * 4 + 3] + w1.x) * w1.y;
        }
        p0 += __shfl_xor_sync(0xffffffffu, p0, 1);
        p0 += __shfl_xor_sync(0xffffffffu, p0, 2);
        p1 += __shfl_xor_sync(0xffffffffu, p1, 1);
        p1 += __shfl_xor_sync(0xffffffffu, p1, 2);
        if ((lane & 3) == 0) {
            int r = tile * 16 + g;
            s_out[r]     = p0 + bias2;
            s_out[r + 8] = p1 + bias2;
        }
    }
}

// ---------------------------------------------------------------------------
// Pass 2: per-segment softmax, IN PLACE (s -> attention weights)
// ---------------------------------------------------------------------------
__global__ void softmax_kernel(float* __restrict__ sw) {
    __shared__ float red[8];
    __shared__ float bcast[2];
    const int b   = blockIdx.x;
    const int s0  = g_start[b];
    const int s1  = g_start[b + 1];
    const int tid = threadIdx.x;

    float m = -3.402823466e38f;
    for (int i = s0 + tid; i < s1; i += 256) m = fmaxf(m, sw[i]);
#pragma unroll
    for (int o = 16; o; o >>= 1) m = fmaxf(m, __shfl_xor_sync(0xffffffffu, m, o));
    if ((tid & 31) == 0) red[tid >> 5] = m;
    __syncthreads();
    if (tid == 0) {
        float v = red[0];
#pragma unroll
        for (int i = 1; i < 8; i++) v = fmaxf(v, red[i]);
        bcast[0] = v;
    }
    __syncthreads();
    m = bcast[0];

    float sum = 0.0f;
    for (int i = s0 + tid; i < s1; i += 256) sum += expf(sw[i] - m);
#pragma unroll
    for (int o = 16; o; o >>= 1) sum += __shfl_xor_sync(0xffffffffu, sum, o);
    __syncthreads();
    if ((tid & 31) == 0) red[tid >> 5] = sum;
    __syncthreads();
    if (tid == 0) {
        float v = 0.0f;
#pragma unroll
        for (int i = 0; i < 8; i++) v += red[i];
        bcast[1] = v;
    }
    __syncthreads();
    const float denom = bcast[1];

    for (int i = s0 + tid; i < s1; i += 256)
        sw[i] = expf(sw[i] - m) / denom;
}

// ---------------------------------------------------------------------------
// Pass 3: context[b,:] = sum_{n in segment} w[n] * x[n,:]
// One block per segment, one thread per feature column (perfectly coalesced).
// ---------------------------------------------------------------------------
__global__ void pool_kernel(const float* __restrict__ x,
                            const float* __restrict__ w,
                            float* __restrict__ ctx) {
    const int b  = blockIdx.x;
    const int d  = threadIdx.x;
    const int s0 = g_start[b];
    const int s1 = g_start[b + 1];

    float acc = 0.0f;
    const float* xp = x + (size_t)s0 * D_IN + d;
    int n = s0;
    for (; n + 4 <= s1; n += 4) {
        float w0 = __ldg(w + n);
        float w1 = __ldg(w + n + 1);
        float w2 = __ldg(w + n + 2);
        float w3 = __ldg(w + n + 3);
        acc += w0 * xp[0];
        acc += w1 * xp[D_IN];
        acc += w2 * xp[2 * D_IN];
        acc += w3 * xp[3 * D_IN];
        xp += 4 * D_IN;
    }
    for (; n < s1; n++) {
        acc += __ldg(w + n) * xp[0];
        xp += D_IN;
    }
    ctx[b * D_IN + d] = acc;
}

// ---------------------------------------------------------------------------
// launch: outputs are [context_vectors (B*D)] then [attention_weights (N)]
// ---------------------------------------------------------------------------
extern "C" void kernel_launch(void* const* d_in, const int* in_sizes, int n_in,
                              void* d_out, int out_size) {
    const float* x   = (const float*)d_in[0];
    const int*   seg = (const int*)d_in[1];
    const float* W1  = (const float*)d_in[2];
    const float* b1  = (const float*)d_in[3];
    const float* W2  = (const float*)d_in[4];
    const float* b2  = (const float*)d_in[5];

    float* ctx = (float*)d_out;                       // [B, D]
    float* sw  = ctx + (size_t)B_SEG * D_IN;          // [N] : logits then weights

    cudaFuncSetAttribute(logits_kernel,
                         cudaFuncAttributeMaxDynamicSharedMemorySize, SMEM_BYTES);

    find_starts_kernel<<<(B_SEG + 256) / 256, 256>>>(seg);
    logits_kernel<<<152, 512, SMEM_BYTES>>>(x, W1, b1, W2, b2, sw);
    softmax_kernel<<<B_SEG, 256>>>(sw);
    pool_kernel<<<B_SEG, 256>>>(x, sw, ctx);
}

// round 8
// speedup vs baseline: 1.0013x; 1.0013x over previous
#include <cuda_runtime.h>
#include <cstdint>
#include <cstddef>

// Problem constants (fixed by the dataset)
#define N_TOK   1048576
#define B_SEG   4096
#define D_IN    256
#define H_MLP   128
#define N_TILES (N_TOK / 16)      // 65536 tiles of 16 tokens

// smem: 16 kt * 16 nt * 32 lanes * 16B packed W1 fragments + 128 float2 (b1,W2)
#define BFRAG_ELEMS (16 * 16 * 32)
#define SMEM_BYTES  (BFRAG_ELEMS * 16 + H_MLP * 8)

__device__ int g_start[B_SEG + 1];

// ---------------------------------------------------------------------------
// helpers
// ---------------------------------------------------------------------------
__device__ __forceinline__ uint32_t pack_bf16x2(float hi, float lo) {
    // result = { upper16 = bf16(hi), lower16 = bf16(lo) }
    uint32_t r;
    asm("cvt.rn.bf16x2.f32 %0, %1, %2;" : "=r"(r) : "f"(hi), "f"(lo));
    return r;
}

__device__ __forceinline__ void mma_bf16(float d[4],
                                         uint32_t a0, uint32_t a1, uint32_t a2, uint32_t a3,
                                         uint32_t b0, uint32_t b1) {
    asm volatile(
        "mma.sync.aligned.m16n8k16.row.col.f32.bf16.bf16.f32 "
        "{%0,%1,%2,%3}, {%4,%5,%6,%7}, {%8,%9}, {%0,%1,%2,%3};\n"
        : "+f"(d[0]), "+f"(d[1]), "+f"(d[2]), "+f"(d[3])
        : "r"(a0), "r"(a1), "r"(a2), "r"(a3), "r"(b0), "r"(b1));
}

__device__ __forceinline__ float fast_tanh(float v) {
    // tanh(v) = 1 - 2/(exp(2v)+1); saturates correctly at +/-inf of the exp.
    float e = __expf(2.0f * v);
    return 1.0f - __fdividef(2.0f, e + 1.0f);
}

// ---------------------------------------------------------------------------
// Pass 0: segment start offsets via binary search (ids are sorted)
// ---------------------------------------------------------------------------
__global__ void find_starts_kernel(const int* __restrict__ seg) {
    int b = blockIdx.x * blockDim.x + threadIdx.x;
    if (b > B_SEG) return;
    if (b == B_SEG) { g_start[B_SEG] = N_TOK; return; }
    int lo = 0, hi = N_TOK;
    while (lo < hi) {
        int mid = (lo + hi) >> 1;
        if (seg[mid] < b) lo = mid + 1; else hi = mid;
    }
    g_start[b] = lo;
}

// ---------------------------------------------------------------------------
// Pass 1: s[n] = tanh(x @ W1 + b1) @ W2 + b2   via split-bf16 tensor-core GEMM
// One warp computes a 16-token x 128-hidden tile; K=256 in 16 steps.
// W1 fragments (hi+lo bf16 split) pre-packed in smem in mma B-fragment layout.
// ---------------------------------------------------------------------------
__global__ __launch_bounds__(512, 1)
void logits_kernel(const float* __restrict__ x,
                   const float* __restrict__ W1,
                   const float* __restrict__ b1,
                   const float* __restrict__ W2,
                   const float* __restrict__ b2,
                   float* __restrict__ s_out) {
    extern __shared__ unsigned char smem_raw[];
    uint4*  bfrag = reinterpret_cast<uint4*>(smem_raw);
    float2* pw    = reinterpret_cast<float2*>(smem_raw + BFRAG_ELEMS * 16);

    const int tid = threadIdx.x;

    // --- pack W1 (hi/lo bf16 split) into B-fragment layout ---
    for (int e = tid; e < BFRAG_ELEMS; e += 512) {
        int kt = e >> 9;
        int nt = (e >> 5) & 15;
        int ln = e & 31;
        int k0 = kt * 16 + (ln & 3) * 2;      // k index of b0
        int nn = nt * 8 + (ln >> 2);          // n index
        float v0 = W1[(k0    ) * H_MLP + nn];
        float v1 = W1[(k0 + 1) * H_MLP + nn];
        float v2 = W1[(k0 + 8) * H_MLP + nn];
        float v3 = W1[(k0 + 9) * H_MLP + nn];
        uint32_t h0 = pack_bf16x2(v1, v0);
        uint32_t h1 = pack_bf16x2(v3, v2);
        float r0 = v0 - __uint_as_float(h0 << 16);
        float r1 = v1 - __uint_as_float(h0 & 0xffff0000u);
        float r2 = v2 - __uint_as_float(h1 << 16);
        float r3 = v3 - __uint_as_float(h1 & 0xffff0000u);
        uint32_t l0 = pack_bf16x2(r1, r0);
        uint32_t l1 = pack_bf16x2(r3, r2);
        bfrag[e] = make_uint4(h0, h1, l0, l1);
    }
    for (int n = tid; n < H_MLP; n += 512)
        pw[n] = make_float2(b1[n], W2[n]);
    const float bias2 = b2[0];
    __syncthreads();

    const int warp  = tid >> 5;
    const int lane  = tid & 31;
    const int g     = lane >> 2;          // row within groups
    const int cbase = (lane & 3) * 2;     // col pair base

    for (int tile = blockIdx.x * 16 + warp; tile < N_TILES; tile += gridDim.x * 16) {
        const float* xr0 = x + (size_t)(tile * 16 + g) * D_IN;
        const float* xr1 = xr0 + 8 * D_IN;

        float acc[64];
#pragma unroll
        for (int i = 0; i < 64; i++) acc[i] = 0.0f;

        // prefetch kt = 0
        float2 q0 = *reinterpret_cast<const float2*>(xr0 + cbase);
        float2 q1 = *reinterpret_cast<const float2*>(xr0 + cbase + 8);
        float2 q2 = *reinterpret_cast<const float2*>(xr1 + cbase);
        float2 q3 = *reinterpret_cast<const float2*>(xr1 + cbase + 8);

#pragma unroll 1
        for (int kt = 0; kt < 16; kt++) {
            float2 c0 = q0, c1 = q1, c2 = q2, c3 = q3;
            if (kt < 15) {
                int c = (kt + 1) * 16 + cbase;
                q0 = *reinterpret_cast<const float2*>(xr0 + c);
                q1 = *reinterpret_cast<const float2*>(xr0 + c + 8);
                q2 = *reinterpret_cast<const float2*>(xr1 + c);
                q3 = *reinterpret_cast<const float2*>(xr1 + c + 8);
            }
            // A fragments: a0=(r0,c..), a1=(r1,c..), a2=(r0,c+8..), a3=(r1,c+8..)
            uint32_t ah0 = pack_bf16x2(c0.y, c0.x);
            uint32_t ah1 = pack_bf16x2(c2.y, c2.x);
            uint32_t ah2 = pack_bf16x2(c1.y, c1.x);
            uint32_t ah3 = pack_bf16x2(c3.y, c3.x);
            uint32_t al0 = pack_bf16x2(c0.y - __uint_as_float(ah0 & 0xffff0000u),
                                       c0.x - __uint_as_float(ah0 << 16));
            uint32_t al1 = pack_bf16x2(c2.y - __uint_as_float(ah1 & 0xffff0000u),
                                       c2.x - __uint_as_float(ah1 << 16));
            uint32_t al2 = pack_bf16x2(c1.y - __uint_as_float(ah2 & 0xffff0000u),
                                       c1.x - __uint_as_float(ah2 << 16));
            uint32_t al3 = pack_bf16x2(c3.y - __uint_as_float(ah3 & 0xffff0000u),
                                       c3.x - __uint_as_float(ah3 << 16));

            const uint4* bp = bfrag + kt * 512 + lane;
#pragma unroll
            for (int nt = 0; nt < 16; nt++) {
                uint4 bb = bp[nt * 32];             // one conflict-free LDS.128
                float* d = &acc[nt * 4];
                mma_bf16(d, ah0, ah1, ah2, ah3, bb.x, bb.y);  // x_hi * W_hi
                mma_bf16(d, al0, al1, al2, al3, bb.x, bb.y);  // x_lo * W_hi
                mma_bf16(d, ah0, ah1, ah2, ah3, bb.z, bb.w);  // x_hi * W_lo
            }
        }

        // epilogue: s = sum_n tanh(h + b1) * W2
        float p0 = 0.0f, p1 = 0.0f;
#pragma unroll
        for (int nt = 0; nt < 16; nt++) {
            int n0 = nt * 8 + cbase;
            float2 w0 = pw[n0];
            float2 w1 = pw[n0 + 1];
            p0 += fast_tanh(acc[nt * 4 + 0] + w0.x) * w0.y;
            p0 += fast_tanh(acc[nt * 4 + 1] + w1.x) * w1.y;
            p1 += fast_tanh(acc[nt * 4 + 2] + w0.x) * w0.y;
            p1 += fast_tanh(acc[nt * 4 + 3] + w1.x) * w1.y;
        }
        p0 += __shfl_xor_sync(0xffffffffu, p0, 1);
        p0 += __shfl_xor_sync(0xffffffffu, p0, 2);
        p1 += __shfl_xor_sync(0xffffffffu, p1, 1);
        p1 += __shfl_xor_sync(0xffffffffu, p1, 2);
        if ((lane & 3) == 0) {
            int r = tile * 16 + g;
            s_out[r]     = p0 + bias2;
            s_out[r + 8] = p1 + bias2;
        }
    }
}

// ---------------------------------------------------------------------------
// Pass 2: per-segment softmax, IN PLACE (s -> attention weights)
// ---------------------------------------------------------------------------
__global__ void softmax_kernel(float* __restrict__ sw) {
    __shared__ float red[8];
    __shared__ float bcast[2];
    const int b   = blockIdx.x;
    const int s0  = g_start[b];
    const int s1  = g_start[b + 1];
    const int tid = threadIdx.x;

    float m = -3.402823466e38f;
    for (int i = s0 + tid; i < s1; i += 256) m = fmaxf(m, sw[i]);
#pragma unroll
    for (int o = 16; o; o >>= 1) m = fmaxf(m, __shfl_xor_sync(0xffffffffu, m, o));
    if ((tid & 31) == 0) red[tid >> 5] = m;
    __syncthreads();
    if (tid == 0) {
        float v = red[0];
#pragma unroll
        for (int i = 1; i < 8; i++) v = fmaxf(v, red[i]);
        bcast[0] = v;
    }
    __syncthreads();
    m = bcast[0];

    float sum = 0.0f;
    for (int i = s0 + tid; i < s1; i += 256) sum += expf(sw[i] - m);
#pragma unroll
    for (int o = 16; o; o >>= 1) sum += __shfl_xor_sync(0xffffffffu, sum, o);
    __syncthreads();
    if ((tid & 31) == 0) red[tid >> 5] = sum;
    __syncthreads();
    if (tid == 0) {
        float v = 0.0f;
#pragma unroll
        for (int i = 0; i < 8; i++) v += red[i];
        bcast[1] = v;
    }
    __syncthreads();
    const float denom = bcast[1];

    for (int i = s0 + tid; i < s1; i += 256)
        sw[i] = expf(sw[i] - m) / denom;
}

// ---------------------------------------------------------------------------
// Pass 3: context[b,:] = sum_{n in segment} w[n] * x[n,:]
// One block per segment, one thread per feature column (perfectly coalesced).
// ---------------------------------------------------------------------------
__global__ void pool_kernel(const float* __restrict__ x,
                            const float* __restrict__ w,
                            float* __restrict__ ctx) {
    const int b  = blockIdx.x;
    const int d  = threadIdx.x;
    const int s0 = g_start[b];
    const int s1 = g_start[b + 1];

    float acc = 0.0f;
    const float* xp = x + (size_t)s0 * D_IN + d;
    int n = s0;
    for (; n + 4 <= s1; n += 4) {
        float w0 = __ldg(w + n);
        float w1 = __ldg(w + n + 1);
        float w2 = __ldg(w + n + 2);
        float w3 = __ldg(w + n + 3);
        acc += w0 * xp[0];
        acc += w1 * xp[D_IN];
        acc += w2 * xp[2 * D_IN];
        acc += w3 * xp[3 * D_IN];
        xp += 4 * D_IN;
    }
    for (; n < s1; n++) {
        acc += __ldg(w + n) * xp[0];
        xp += D_IN;
    }
    ctx[b * D_IN + d] = acc;
}

// ---------------------------------------------------------------------------
// launch: outputs are [context_vectors (B*D)] then [attention_weights (N)]
// ---------------------------------------------------------------------------
extern "C" void kernel_launch(void* const* d_in, const int* in_sizes, int n_in,
                              void* d_out, int out_size) {
    const float* x   = (const float*)d_in[0];
    const int*   seg = (const int*)d_in[1];
    const float* W1  = (const float*)d_in[2];
    const float* b1  = (const float*)d_in[3];
    const float* W2  = (const float*)d_in[4];
    const float* b2  = (const float*)d_in[5];

    float* ctx = (float*)d_out;                       // [B, D]
    float* sw  = ctx + (size_t)B_SEG * D_IN;          // [N] : logits then weights

    cudaFuncSetAttribute(logits_kernel,
                         cudaFuncAttributeMaxDynamicSharedMemorySize, SMEM_BYTES);

    find_starts_kernel<<<(B_SEG + 256) / 256, 256>>>(seg);
    logits_kernel<<<152, 512, SMEM_BYTES>>>(x, W1, b1, W2, b2, sw);
    softmax_kernel<<<B_SEG, 256>>>(sw);
    pool_kernel<<<B_SEG, 256>>>(x, sw, ctx);
}

// round 9
// speedup vs baseline: 1.0014x; 1.0000x over previous
#include <cuda_runtime.h>
#include <cstdint>
#include <cstddef>

// Problem constants (fixed by the dataset)
#define N_TOK   1048576
#define B_SEG   4096
#define D_IN    256
#define H_MLP   128
#define N_TILES (N_TOK / 16)      // 65536 tiles of 16 tokens

// smem: 16 kt * 16 nt * 32 lanes * 16B packed W1 fragments + 128 float2 (b1,W2)
#define BFRAG_ELEMS (16 * 16 * 32)
#define SMEM_BYTES  (BFRAG_ELEMS * 16 + H_MLP * 8)

__device__ int g_start[B_SEG + 1];

// ---------------------------------------------------------------------------
// helpers
// ---------------------------------------------------------------------------
__device__ __forceinline__ uint32_t pack_bf16x2(float hi, float lo) {
    // result = { upper16 = bf16(hi), lower16 = bf16(lo) }
    uint32_t r;
    asm("cvt.rn.bf16x2.f32 %0, %1, %2;" : "=r"(r) : "f"(hi), "f"(lo));
    return r;
}

__device__ __forceinline__ void mma_bf16(float d[4],
                                         uint32_t a0, uint32_t a1, uint32_t a2, uint32_t a3,
                                         uint32_t b0, uint32_t b1) {
    asm volatile(
        "mma.sync.aligned.m16n8k16.row.col.f32.bf16.bf16.f32 "
        "{%0,%1,%2,%3}, {%4,%5,%6,%7}, {%8,%9}, {%0,%1,%2,%3};\n"
        : "+f"(d[0]), "+f"(d[1]), "+f"(d[2]), "+f"(d[3])
        : "r"(a0), "r"(a1), "r"(a2), "r"(a3), "r"(b0), "r"(b1));
}

__device__ __forceinline__ float fast_tanh(float v) {
    // tanh(v) = 1 - 2/(exp(2v)+1); saturates correctly at +/-inf of the exp.
    float e = __expf(2.0f * v);
    return 1.0f - __fdividef(2.0f, e + 1.0f);
}

// ---------------------------------------------------------------------------
// Pass 0: segment start offsets via binary search (ids are sorted)
// ---------------------------------------------------------------------------
__global__ void find_starts_kernel(const int* __restrict__ seg) {
    int b = blockIdx.x * blockDim.x + threadIdx.x;
    if (b > B_SEG) return;
    if (b == B_SEG) { g_start[B_SEG] = N_TOK; return; }
    int lo = 0, hi = N_TOK;
    while (lo < hi) {
        int mid = (lo + hi) >> 1;
        if (seg[mid] < b) lo = mid + 1; else hi = mid;
    }
    g_start[b] = lo;
}

// ---------------------------------------------------------------------------
// Pass 1: s[n] = tanh(x @ W1 + b1) @ W2 + b2   via split-bf16 tensor-core GEMM
// One warp computes a 16-token x 128-hidden tile; K=256 in 16 steps.
// W1 fragments (hi+lo bf16 split) pre-packed in smem in mma B-fragment layout.
// ---------------------------------------------------------------------------
__global__ __launch_bounds__(512, 1)
void logits_kernel(const float* __restrict__ x,
                   const float* __restrict__ W1,
                   const float* __restrict__ b1,
                   const float* __restrict__ W2,
                   const float* __restrict__ b2,
                   float* __restrict__ s_out) {
    extern __shared__ unsigned char smem_raw[];
    uint4*  bfrag = reinterpret_cast<uint4*>(smem_raw);
    float2* pw    = reinterpret_cast<float2*>(smem_raw + BFRAG_ELEMS * 16);

    const int tid = threadIdx.x;

    // --- pack W1 (hi/lo bf16 split) into B-fragment layout ---
    for (int e = tid; e < BFRAG_ELEMS; e += 512) {
        int kt = e >> 9;
        int nt = (e >> 5) & 15;
        int ln = e & 31;
        int k0 = kt * 16 + (ln & 3) * 2;      // k index of b0
        int nn = nt * 8 + (ln >> 2);          // n index
        float v0 = W1[(k0    ) * H_MLP + nn];
        float v1 = W1[(k0 + 1) * H_MLP + nn];
        float v2 = W1[(k0 + 8) * H_MLP + nn];
        float v3 = W1[(k0 + 9) * H_MLP + nn];
        uint32_t h0 = pack_bf16x2(v1, v0);
        uint32_t h1 = pack_bf16x2(v3, v2);
        float r0 = v0 - __uint_as_float(h0 << 16);
        float r1 = v1 - __uint_as_float(h0 & 0xffff0000u);
        float r2 = v2 - __uint_as_float(h1 << 16);
        float r3 = v3 - __uint_as_float(h1 & 0xffff0000u);
        uint32_t l0 = pack_bf16x2(r1, r0);
        uint32_t l1 = pack_bf16x2(r3, r2);
        bfrag[e] = make_uint4(h0, h1, l0, l1);
    }
    for (int n = tid; n < H_MLP; n += 512)
        pw[n] = make_float2(b1[n], W2[n]);
    const float bias2 = b2[0];
    __syncthreads();

    const int warp  = tid >> 5;
    const int lane  = tid & 31;
    const int g     = lane >> 2;          // row within groups
    const int cbase = (lane & 3) * 2;     // col pair base

    for (int tile = blockIdx.x * 16 + warp; tile < N_TILES; tile += gridDim.x * 16) {
        const float* xr0 = x + (size_t)(tile * 16 + g) * D_IN;
        const float* xr1 = xr0 + 8 * D_IN;

        float acc[64];
#pragma unroll
        for (int i = 0; i < 64; i++) acc[i] = 0.0f;

        // prefetch kt = 0
        float2 q0 = *reinterpret_cast<const float2*>(xr0 + cbase);
        float2 q1 = *reinterpret_cast<const float2*>(xr0 + cbase + 8);
        float2 q2 = *reinterpret_cast<const float2*>(xr1 + cbase);
        float2 q3 = *reinterpret_cast<const float2*>(xr1 + cbase + 8);

#pragma unroll 1
        for (int kt = 0; kt < 16; kt++) {
            float2 c0 = q0, c1 = q1, c2 = q2, c3 = q3;
            if (kt < 15) {
                int c = (kt + 1) * 16 + cbase;
                q0 = *reinterpret_cast<const float2*>(xr0 + c);
                q1 = *reinterpret_cast<const float2*>(xr0 + c + 8);
                q2 = *reinterpret_cast<const float2*>(xr1 + c);
                q3 = *reinterpret_cast<const float2*>(xr1 + c + 8);
            }
            // A fragments: a0=(r0,c..), a1=(r1,c..), a2=(r0,c+8..), a3=(r1,c+8..)
            uint32_t ah0 = pack_bf16x2(c0.y, c0.x);
            uint32_t ah1 = pack_bf16x2(c2.y, c2.x);
            uint32_t ah2 = pack_bf16x2(c1.y, c1.x);
            uint32_t ah3 = pack_bf16x2(c3.y, c3.x);
            uint32_t al0 = pack_bf16x2(c0.y - __uint_as_float(ah0 & 0xffff0000u),
                                       c0.x - __uint_as_float(ah0 << 16));
            uint32_t al1 = pack_bf16x2(c2.y - __uint_as_float(ah1 & 0xffff0000u),
                                       c2.x - __uint_as_float(ah1 << 16));
            uint32_t al2 = pack_bf16x2(c1.y - __uint_as_float(ah2 & 0xffff0000u),
                                       c1.x - __uint_as_float(ah2 << 16));
            uint32_t al3 = pack_bf16x2(c3.y - __uint_as_float(ah3 & 0xffff0000u),
                                       c3.x - __uint_as_float(ah3 << 16));

            const uint4* bp = bfrag + kt * 512 + lane;
#pragma unroll
            for (int nt = 0; nt < 16; nt++) {
                uint4 bb = bp[nt * 32];             // one conflict-free LDS.128
                float* d = &acc[nt * 4];
                mma_bf16(d, ah0, ah1, ah2, ah3, bb.x, bb.y);  // x_hi * W_hi
                mma_bf16(d, al0, al1, al2, al3, bb.x, bb.y);  // x_lo * W_hi
                mma_bf16(d, ah0, ah1, ah2, ah3, bb.z, bb.w);  // x_hi * W_lo
            }
        }

        // epilogue: s = sum_n tanh(h + b1) * W2
        float p0 = 0.0f, p1 = 0.0f;
#pragma unroll
        for (int nt = 0; nt < 16; nt++) {
            int n0 = nt * 8 + cbase;
            float2 w0 = pw[n0];
            float2 w1 = pw[n0 + 1];
            p0 += fast_tanh(acc[nt * 4 + 0] + w0.x) * w0.y;
            p0 += fast_tanh(acc[nt * 4 + 1] + w1.x) * w1.y;
            p1 += fast_tanh(acc[nt * 4 + 2] + w0.x) * w0.y;
            p1 += fast_tanh(acc[nt * 4 + 3] + w1.x) * w1.y;
        }
        p0 += __shfl_xor_sync(0xffffffffu, p0, 1);
        p0 += __shfl_xor_sync(0xffffffffu, p0, 2);
        p1 += __shfl_xor_sync(0xffffffffu, p1, 1);
        p1 += __shfl_xor_sync(0xffffffffu, p1, 2);
        if ((lane & 3) == 0) {
            int r = tile * 16 + g;
            s_out[r]     = p0 + bias2;
            s_out[r + 8] = p1 + bias2;
        }
    }
}

// ---------------------------------------------------------------------------
// Pass 2: per-segment softmax, IN PLACE (s -> attention weights)
// ---------------------------------------------------------------------------
__global__ void softmax_kernel(float* __restrict__ sw) {
    __shared__ float red[8];
    __shared__ float bcast[2];
    const int b   = blockIdx.x;
    const int s0  = g_start[b];
    const int s1  = g_start[b + 1];
    const int tid = threadIdx.x;

    float m = -3.402823466e38f;
    for (int i = s0 + tid; i < s1; i += 256) m = fmaxf(m, sw[i]);
#pragma unroll
    for (int o = 16; o; o >>= 1) m = fmaxf(m, __shfl_xor_sync(0xffffffffu, m, o));
    if ((tid & 31) == 0) red[tid >> 5] = m;
    __syncthreads();
    if (tid == 0) {
        float v = red[0];
#pragma unroll
        for (int i = 1; i < 8; i++) v = fmaxf(v, red[i]);
        bcast[0] = v;
    }
    __syncthreads();
    m = bcast[0];

    float sum = 0.0f;
    for (int i = s0 + tid; i < s1; i += 256) sum += expf(sw[i] - m);
#pragma unroll
    for (int o = 16; o; o >>= 1) sum += __shfl_xor_sync(0xffffffffu, sum, o);
    __syncthreads();
    if ((tid & 31) == 0) red[tid >> 5] = sum;
    __syncthreads();
    if (tid == 0) {
        float v = 0.0f;
#pragma unroll
        for (int i = 0; i < 8; i++) v += red[i];
        bcast[1] = v;
    }
    __syncthreads();
    const float denom = bcast[1];

    for (int i = s0 + tid; i < s1; i += 256)
        sw[i] = expf(sw[i] - m) / denom;
}

// ---------------------------------------------------------------------------
// Pass 3: context[b,:] = sum_{n in segment} w[n] * x[n,:]
// One block per segment, one thread per feature column (perfectly coalesced).
// ---------------------------------------------------------------------------
__global__ void pool_kernel(const float* __restrict__ x,
                            const float* __restrict__ w,
                            float* __restrict__ ctx) {
    const int b  = blockIdx.x;
    const int d  = threadIdx.x;
    const int s0 = g_start[b];
    const int s1 = g_start[b + 1];

    float acc = 0.0f;
    const float* xp = x + (size_t)s0 * D_IN + d;
    int n = s0;
    for (; n + 4 <= s1; n += 4) {
        float w0 = __ldg(w + n);
        float w1 = __ldg(w + n + 1);
        float w2 = __ldg(w + n + 2);
        float w3 = __ldg(w + n + 3);
        acc += w0 * xp[0];
        acc += w1 * xp[D_IN];
        acc += w2 * xp[2 * D_IN];
        acc += w3 * xp[3 * D_IN];
        xp += 4 * D_IN;
    }
    for (; n < s1; n++) {
        acc += __ldg(w + n) * xp[0];
        xp += D_IN;
    }
    ctx[b * D_IN + d] = acc;
}

// ---------------------------------------------------------------------------
// launch: outputs are [context_vectors (B*D)] then [attention_weights (N)]
// ---------------------------------------------------------------------------
extern "C" void kernel_launch(void* const* d_in, const int* in_sizes, int n_in,
                              void* d_out, int out_size) {
    const float* x   = (const float*)d_in[0];
    const int*   seg = (const int*)d_in[1];
    const float* W1  = (const float*)d_in[2];
    const float* b1  = (const float*)d_in[3];
    const float* W2  = (const float*)d_in[4];
    const float* b2  = (const float*)d_in[5];

    float* ctx = (float*)d_out;                       // [B, D]
    float* sw  = ctx + (size_t)B_SEG * D_IN;          // [N] : logits then weights

    cudaFuncSetAttribute(logits_kernel,
                         cudaFuncAttributeMaxDynamicSharedMemorySize, SMEM_BYTES);

    find_starts_kernel<<<(B_SEG + 256) / 256, 256>>>(seg);
    logits_kernel<<<152, 512, SMEM_BYTES>>>(x, W1, b1, W2, b2, sw);
    softmax_kernel<<<B_SEG, 256>>>(sw);
    pool_kernel<<<B_SEG, 256>>>(x, sw, ctx);
}

// round 12
// speedup vs baseline: 1.4056x; 1.4037x over previous
#include <cuda_runtime.h>
#include <cuda_fp16.h>
#include <cstdint>
#include <cstddef>

// Problem constants (fixed by the dataset)
#define N_TOK   1048576
#define B_SEG   4096
#define D_IN    256
#define H_MLP   128
#define N_TILES (N_TOK / 16)      // 65536 tiles of 16 tokens
#define GRID_LG 152

// smem layout for logits kernel
//  [0, 65536)        : W1_hi fp16 B-fragments, uint2 x (16 kt * 16 nt * 32 ln)
//  [65536, 66560)    : 128 x float2 {b1, W2}
//  [66560, 201728)   : per-warp staging for fp16(x) tile: 16 warps x 16 rows x 132 half2
#define BFRAG_ELEMS (16 * 16 * 32)
#define SM_PW       (BFRAG_ELEMS * 8)
#define SM_STAGE    (SM_PW + H_MLP * 8)
#define STAGE_ROW   132                       // 128 data half2 + 4 pad (bank-conflict-free)
#define STAGE_WARP  (16 * STAGE_ROW)          // half2 per warp
#define SMEM_LG     (SM_STAGE + 16 * STAGE_WARP * 4)

__device__ int g_start[B_SEG + 1];
// fp16 copy of x, written by the logits pass, consumed by the pool pass (512 MB scratch)
__device__ __half2 g_xf16[(size_t)N_TOK * (D_IN / 2)];

// ---------------------------------------------------------------------------
// helpers
// ---------------------------------------------------------------------------
__device__ __forceinline__ uint32_t pack_f16x2(float lo, float hi) {
    // lower 16 bits = fp16(lo), upper = fp16(hi)
    uint32_t r;
    asm("cvt.rn.f16x2.f32 %0, %1, %2;" : "=r"(r) : "f"(hi), "f"(lo));
    return r;
}

// pack (v0,v1) to fp16x2 and produce the fp16x2 of the exact fp32 residuals
__device__ __forceinline__ void cvt_pair(float v0, float v1, uint32_t& h, uint32_t& l) {
    h = pack_f16x2(v0, v1);
    __half2 hh = *reinterpret_cast<__half2*>(&h);
    float2 hf = __half22float2(hh);
    l = pack_f16x2(v0 - hf.x, v1 - hf.y);
}

__device__ __forceinline__ void mma_f16(float d[4],
                                        uint32_t a0, uint32_t a1, uint32_t a2, uint32_t a3,
                                        uint32_t b0, uint32_t b1) {
    asm volatile(
        "mma.sync.aligned.m16n8k16.row.col.f32.f16.f16.f32 "
        "{%0,%1,%2,%3}, {%4,%5,%6,%7}, {%8,%9}, {%0,%1,%2,%3};\n"
        : "+f"(d[0]), "+f"(d[1]), "+f"(d[2]), "+f"(d[3])
        : "r"(a0), "r"(a1), "r"(a2), "r"(a3), "r"(b0), "r"(b1));
}

__device__ __forceinline__ float fast_tanh(float v) {
    float e = __expf(2.0f * v);
    return 1.0f - __fdividef(2.0f, e + 1.0f);
}

// ---------------------------------------------------------------------------
// Pass 0: segment start offsets via binary search (ids are sorted)
// ---------------------------------------------------------------------------
__global__ void find_starts_kernel(const int* __restrict__ seg) {
    int b = blockIdx.x * blockDim.x + threadIdx.x;
    if (b > B_SEG) return;
    if (b == B_SEG) { g_start[B_SEG] = N_TOK; return; }
    int lo = 0, hi = N_TOK;
    while (lo < hi) {
        int mid = (lo + hi) >> 1;
        if (seg[mid] < b) lo = mid + 1; else hi = mid;
    }
    g_start[b] = lo;
}

// ---------------------------------------------------------------------------
// Pass 1: s[n] = tanh(x @ W1 + b1) @ W2 + b2   via 2-MMA fp16 split GEMM.
//   s ≈ (x_hi @ W_hi + x_lo @ W_hi)            (dropped x_hi@W_lo ~ 1e-4 rel)
// One warp computes a 16-token x 128-hidden tile; K=256 in 16 steps.
// Side product: fp16(x) written coalesced to g_xf16 for the pool pass.
// ---------------------------------------------------------------------------
__global__ __launch_bounds__(512, 1)
void logits_kernel(const float* __restrict__ x,
                   const float* __restrict__ W1,
                   const float* __restrict__ b1,
                   const float* __restrict__ W2,
                   const float* __restrict__ b2,
                   float* __restrict__ s_out) {
    extern __shared__ unsigned char smem_raw[];
    uint2*  bfrag = reinterpret_cast<uint2*>(smem_raw);
    float2* pw    = reinterpret_cast<float2*>(smem_raw + SM_PW);

    const int tid = threadIdx.x;

    // --- pack W1 (fp16 hi only) into B-fragment layout ---
    for (int e = tid; e < BFRAG_ELEMS; e += 512) {
        int kt = e >> 9;
        int nt = (e >> 5) & 15;
        int ln = e & 31;
        int k0 = kt * 16 + (ln & 3) * 2;      // k index of b0
        int nn = nt * 8 + (ln >> 2);          // n index
        float v0 = W1[(k0    ) * H_MLP + nn];
        float v1 = W1[(k0 + 1) * H_MLP + nn];
        float v2 = W1[(k0 + 8) * H_MLP + nn];
        float v3 = W1[(k0 + 9) * H_MLP + nn];
        bfrag[e] = make_uint2(pack_f16x2(v0, v1), pack_f16x2(v2, v3));
    }
    for (int n = tid; n < H_MLP; n += 512)
        pw[n] = make_float2(b1[n], W2[n]);
    const float bias2 = b2[0];
    __syncthreads();

    const int warp  = tid >> 5;
    const int lane  = tid & 31;
    const int g     = lane >> 2;          // row within 8-row groups
    const int cbase = (lane & 3) * 2;     // col pair base
    const int cb2   = cbase >> 1;         // half2 column index within 8

    __half2* stage = reinterpret_cast<__half2*>(smem_raw + SM_STAGE) + warp * STAGE_WARP;

    for (int tile = blockIdx.x * 16 + warp; tile < N_TILES; tile += GRID_LG * 16) {
        const float* xr0 = x + (size_t)(tile * 16 + g) * D_IN;
        const float* xr1 = xr0 + 8 * D_IN;

        float acc[64];
#pragma unroll
        for (int i = 0; i < 64; i++) acc[i] = 0.0f;

        // prefetch kt = 0
        float2 q0 = *reinterpret_cast<const float2*>(xr0 + cbase);
        float2 q1 = *reinterpret_cast<const float2*>(xr0 + cbase + 8);
        float2 q2 = *reinterpret_cast<const float2*>(xr1 + cbase);
        float2 q3 = *reinterpret_cast<const float2*>(xr1 + cbase + 8);

#pragma unroll 1
        for (int kt = 0; kt < 16; kt++) {
            float2 c0 = q0, c1 = q1, c2 = q2, c3 = q3;
            if (kt < 15) {
                int c = (kt + 1) * 16 + cbase;
                q0 = *reinterpret_cast<const float2*>(xr0 + c);
                q1 = *reinterpret_cast<const float2*>(xr0 + c + 8);
                q2 = *reinterpret_cast<const float2*>(xr1 + c);
                q3 = *reinterpret_cast<const float2*>(xr1 + c + 8);
            }
            // A fragments (fp16 hi + exact residual lo):
            // a0=(r0,k0-7) a1=(r1,k0-7) a2=(r0,k8-15) a3=(r1,k8-15)
            uint32_t ah0, ah1, ah2, ah3, al0, al1, al2, al3;
            cvt_pair(c0.x, c0.y, ah0, al0);
            cvt_pair(c2.x, c2.y, ah1, al1);
            cvt_pair(c1.x, c1.y, ah2, al2);
            cvt_pair(c3.x, c3.y, ah3, al3);

            // stage fp16(x) for the coalesced gmem write (pool pass input)
            {
                int col = kt * 8 + cb2;
                stage[g * STAGE_ROW + col]           = *reinterpret_cast<__half2*>(&ah0);
                stage[g * STAGE_ROW + col + 4]       = *reinterpret_cast<__half2*>(&ah2);
                stage[(g + 8) * STAGE_ROW + col]     = *reinterpret_cast<__half2*>(&ah1);
                stage[(g + 8) * STAGE_ROW + col + 4] = *reinterpret_cast<__half2*>(&ah3);
            }

            const uint2* bp = bfrag + kt * 512 + lane;
#pragma unroll
            for (int nt = 0; nt < 16; nt++) {
                uint2 bb = bp[nt * 32];             // one conflict-free LDS.64
                float* d = &acc[nt * 4];
                mma_f16(d, ah0, ah1, ah2, ah3, bb.x, bb.y);   // x_hi * W_hi
                mma_f16(d, al0, al1, al2, al3, bb.x, bb.y);   // x_lo * W_hi
            }
        }

        // flush staged fp16 x tile: 16 rows x 512B, fully coalesced STG.128
        __syncwarp();
        {
            __half2* dst = g_xf16 + (size_t)tile * 16 * (D_IN / 2);
#pragma unroll
            for (int r = 0; r < 16; r++) {
                uint4 v = *reinterpret_cast<const uint4*>(stage + r * STAGE_ROW + lane * 4);
                *reinterpret_cast<uint4*>(dst + (size_t)r * (D_IN / 2) + lane * 4) = v;
            }
        }

        // epilogue: s = sum_n tanh(h + b1) * W2
        float p0 = 0.0f, p1 = 0.0f;
#pragma unroll
        for (int nt = 0; nt < 16; nt++) {
            int n0 = nt * 8 + cbase;
            float2 w0 = pw[n0];
            float2 w1 = pw[n0 + 1];
            p0 += fast_tanh(acc[nt * 4 + 0] + w0.x) * w0.y;
            p0 += fast_tanh(acc[nt * 4 + 1] + w1.x) * w1.y;
            p1 += fast_tanh(acc[nt * 4 + 2] + w0.x) * w0.y;
            p1 += fast_tanh(acc[nt * 4 + 3] + w1.x) * w1.y;
        }
        p0 += __shfl_xor_sync(0xffffffffu, p0, 1);
        p0 += __shfl_xor_sync(0xffffffffu, p0, 2);
        p1 += __shfl_xor_sync(0xffffffffu, p1, 1);
        p1 += __shfl_xor_sync(0xffffffffu, p1, 2);
        if ((lane & 3) == 0) {
            int r = tile * 16 + g;
            s_out[r]     = p0 + bias2;
            s_out[r + 8] = p1 + bias2;
        }
        __syncwarp();   // staged tile fully consumed before next iteration reuses it
    }
}

// ---------------------------------------------------------------------------
// Pass 2: per-segment softmax, IN PLACE (s -> attention weights)
// ---------------------------------------------------------------------------
__global__ void softmax_kernel(float* __restrict__ sw) {
    __shared__ float red[8];
    __shared__ float bcast[2];
    const int b   = blockIdx.x;
    const int s0  = g_start[b];
    const int s1  = g_start[b + 1];
    const int tid = threadIdx.x;

    float m = -3.402823466e38f;
    for (int i = s0 + tid; i < s1; i += 256) m = fmaxf(m, sw[i]);
#pragma unroll
    for (int o = 16; o; o >>= 1) m = fmaxf(m, __shfl_xor_sync(0xffffffffu, m, o));
    if ((tid & 31) == 0) red[tid >> 5] = m;
    __syncthreads();
    if (tid == 0) {
        float v = red[0];
#pragma unroll
        for (int i = 1; i < 8; i++) v = fmaxf(v, red[i]);
        bcast[0] = v;
    }
    __syncthreads();
    m = bcast[0];

    float sum = 0.0f;
    for (int i = s0 + tid; i < s1; i += 256) sum += expf(sw[i] - m);
#pragma unroll
    for (int o = 16; o; o >>= 1) sum += __shfl_xor_sync(0xffffffffu, sum, o);
    __syncthreads();
    if ((tid & 31) == 0) red[tid >> 5] = sum;
    __syncthreads();
    if (tid == 0) {
        float v = 0.0f;
#pragma unroll
        for (int i = 0; i < 8; i++) v += red[i];
        bcast[1] = v;
    }
    __syncthreads();
    const float denom = bcast[1];

    for (int i = s0 + tid; i < s1; i += 256)
        sw[i] = expf(sw[i] - m) / denom;
}

// ---------------------------------------------------------------------------
// Pass 3: context[b,:] = sum_{n in segment} w[n] * x[n,:]
// Reads the fp16 copy of x (half the DRAM traffic of the fp32 original).
// One block per segment, one thread per half2 feature pair (coalesced 512B/row).
// ---------------------------------------------------------------------------
__global__ void pool_kernel(const float* __restrict__ w,
                            float* __restrict__ ctx) {
    const int b  = blockIdx.x;
    const int d  = threadIdx.x;          // 0..127 -> half2 column
    const int s0 = g_start[b];
    const int s1 = g_start[b + 1];

    float ax = 0.0f, ay = 0.0f;
    const __half2* xp = g_xf16 + (size_t)s0 * (D_IN / 2) + d;
    int n = s0;
    for (; n + 4 <= s1; n += 4) {
        float w0 = __ldg(w + n);
        float w1 = __ldg(w + n + 1);
        float w2 = __ldg(w + n + 2);
        float w3 = __ldg(w + n + 3);
        float2 v0 = __half22float2(xp[0]);
        float2 v1 = __half22float2(xp[D_IN / 2]);
        float2 v2 = __half22float2(xp[2 * (D_IN / 2)]);
        float2 v3 = __half22float2(xp[3 * (D_IN / 2)]);
        ax += w0 * v0.x; ay += w0 * v0.y;
        ax += w1 * v1.x; ay += w1 * v1.y;
        ax += w2 * v2.x; ay += w2 * v2.y;
        ax += w3 * v3.x; ay += w3 * v3.y;
        xp += 4 * (D_IN / 2);
    }
    for (; n < s1; n++) {
        float wn = __ldg(w + n);
        float2 v = __half22float2(xp[0]);
        ax += wn * v.x; ay += wn * v.y;
        xp += D_IN / 2;
    }
    *reinterpret_cast<float2*>(ctx + (size_t)b * D_IN + 2 * d) = make_float2(ax, ay);
}

// ---------------------------------------------------------------------------
// launch: outputs are [context_vectors (B*D)] then [attention_weights (N)]
// ---------------------------------------------------------------------------
extern "C" void kernel_launch(void* const* d_in, const int* in_sizes, int n_in,
                              void* d_out, int out_size) {
    const float* x   = (const float*)d_in[0];
    const int*   seg = (const int*)d_in[1];
    const float* W1  = (const float*)d_in[2];
    const float* b1  = (const float*)d_in[3];
    const float* W2  = (const float*)d_in[4];
    const float* b2  = (const float*)d_in[5];

    float* ctx = (float*)d_out;                       // [B, D]
    float* sw  = ctx + (size_t)B_SEG * D_IN;          // [N] : logits then weights

    cudaFuncSetAttribute(logits_kernel,
                         cudaFuncAttributeMaxDynamicSharedMemorySize, SMEM_LG);

    find_starts_kernel<<<(B_SEG + 256) / 256, 256>>>(seg);
    logits_kernel<<<GRID_LG, 512, SMEM_LG>>>(x, W1, b1, W2, b2, sw);
    softmax_kernel<<<B_SEG, 256>>>(sw);
    pool_kernel<<<B_SEG, 128>>>(sw, ctx);
}

// round 13
// speedup vs baseline: 1.5112x; 1.0751x over previous
#include <cuda_runtime.h>
#include <cuda_fp16.h>
#include <cstdint>
#include <cstddef>

// Problem constants (fixed by the dataset)
#define N_TOK   1048576
#define B_SEG   4096
#define D_IN    256
#define H_MLP   128
#define N_TILES (N_TOK / 16)      // 65536 tiles of 16 tokens
#define GRID_LG 152

// smem layout for logits kernel
//  [0, 65536)        : W1 fp16 B-fragments, uint4 x (16 kt * 8 np * 32 ln)
//  [65536, 66560)    : 128 x float2 {b1, W2}
//  [66560, 201728)   : per-warp staging for fp16(x): 16 warps x 16 rows x 132 half2
#define FRAG4_ELEMS (16 * 8 * 32)
#define SM_PW       (FRAG4_ELEMS * 16)
#define SM_STAGE    (SM_PW + H_MLP * 8)
#define STAGE_ROW   132                       // 128 data half2 + 4 pad
#define STAGE_WARP  (16 * STAGE_ROW)
#define SMEM_LG     (SM_STAGE + 16 * STAGE_WARP * 4)

#define POOL_CAP 3072                          // max cached segment length

__device__ int g_start[B_SEG + 1];
// fp16 copy of x, written by the logits pass, consumed by the pool pass
__device__ __half2 g_xf16[(size_t)N_TOK * (D_IN / 2)];

// ---------------------------------------------------------------------------
// helpers
// ---------------------------------------------------------------------------
__device__ __forceinline__ uint32_t pack_f16x2(float lo, float hi) {
    // lower 16 bits = fp16(lo), upper = fp16(hi)
    uint32_t r;
    asm("cvt.rn.f16x2.f32 %0, %1, %2;" : "=r"(r) : "f"(hi), "f"(lo));
    return r;
}

__device__ __forceinline__ void mma_f16(float d[4],
                                        uint32_t a0, uint32_t a1, uint32_t a2, uint32_t a3,
                                        uint32_t b0, uint32_t b1) {
    asm volatile(
        "mma.sync.aligned.m16n8k16.row.col.f32.f16.f16.f32 "
        "{%0,%1,%2,%3}, {%4,%5,%6,%7}, {%8,%9}, {%0,%1,%2,%3};\n"
        : "+f"(d[0]), "+f"(d[1]), "+f"(d[2]), "+f"(d[3])
        : "r"(a0), "r"(a1), "r"(a2), "r"(a3), "r"(b0), "r"(b1));
}

__device__ __forceinline__ float fast_tanh(float v) {
    float e = __expf(2.0f * v);
    return 1.0f - __fdividef(2.0f, e + 1.0f);
}

__device__ __forceinline__ void stg_cs_128(void* p, uint4 v) {
    asm volatile("st.global.cs.v4.b32 [%0], {%1,%2,%3,%4};"
                 :: "l"(p), "r"(v.x), "r"(v.y), "r"(v.z), "r"(v.w) : "memory");
}

// ---------------------------------------------------------------------------
// Pass 0: segment start offsets via binary search (ids are sorted)
// ---------------------------------------------------------------------------
__global__ void find_starts_kernel(const int* __restrict__ seg) {
    int b = blockIdx.x * blockDim.x + threadIdx.x;
    if (b > B_SEG) return;
    if (b == B_SEG) { g_start[B_SEG] = N_TOK; return; }
    int lo = 0, hi = N_TOK;
    while (lo < hi) {
        int mid = (lo + hi) >> 1;
        if (seg[mid] < b) lo = mid + 1; else hi = mid;
    }
    g_start[b] = lo;
}

// ---------------------------------------------------------------------------
// Pass 1: s[n] = tanh(x @ W1 + b1) @ W2 + b2   via single fp16 MMA GEMM.
// One warp computes a 16-token x 128-hidden tile; K=256 in 16 steps.
// Side product: fp16(x) written coalesced (streaming) to g_xf16 for pooling.
// ---------------------------------------------------------------------------
__global__ __launch_bounds__(512, 1)
void logits_kernel(const float* __restrict__ x,
                   const float* __restrict__ W1,
                   const float* __restrict__ b1,
                   const float* __restrict__ W2,
                   const float* __restrict__ b2,
                   float* __restrict__ s_out) {
    extern __shared__ unsigned char smem_raw[];
    uint4*  frag4 = reinterpret_cast<uint4*>(smem_raw);
    float2* pw    = reinterpret_cast<float2*>(smem_raw + SM_PW);

    const int tid = threadIdx.x;

    // --- pack W1 (fp16) into paired B-fragment layout: uint4 = {nt=2np, nt=2np+1} ---
    for (int e = tid; e < FRAG4_ELEMS; e += 512) {
        int kt = e >> 8;              // 0..15
        int np = (e >> 5) & 7;        // 0..7 (nt pair)
        int ln = e & 31;
        int k0 = kt * 16 + (ln & 3) * 2;
        int nn = np * 16 + (ln >> 2);       // column for nt = 2np
        float v0 = W1[(k0    ) * H_MLP + nn];
        float v1 = W1[(k0 + 1) * H_MLP + nn];
        float v2 = W1[(k0 + 8) * H_MLP + nn];
        float v3 = W1[(k0 + 9) * H_MLP + nn];
        float u0 = W1[(k0    ) * H_MLP + nn + 8];
        float u1 = W1[(k0 + 1) * H_MLP + nn + 8];
        float u2 = W1[(k0 + 8) * H_MLP + nn + 8];
        float u3 = W1[(k0 + 9) * H_MLP + nn + 8];
        frag4[e] = make_uint4(pack_f16x2(v0, v1), pack_f16x2(v2, v3),
                              pack_f16x2(u0, u1), pack_f16x2(u2, u3));
    }
    for (int n = tid; n < H_MLP; n += 512)
        pw[n] = make_float2(b1[n], W2[n]);
    const float bias2 = b2[0];
    __syncthreads();

    const int warp  = tid >> 5;
    const int lane  = tid & 31;
    const int g     = lane >> 2;          // row within 8-row groups
    const int cbase = (lane & 3) * 2;     // col pair base
    const int cb2   = lane & 3;           // half2 column index within 8

    __half2* stage = reinterpret_cast<__half2*>(smem_raw + SM_STAGE) + warp * STAGE_WARP;

    for (int tile = blockIdx.x * 16 + warp; tile < N_TILES; tile += GRID_LG * 16) {
        const float* xr0 = x + (size_t)(tile * 16 + g) * D_IN;
        const float* xr1 = xr0 + 8 * D_IN;

        float acc[64];
#pragma unroll
        for (int i = 0; i < 64; i++) acc[i] = 0.0f;

        // prefetch kt = 0
        float2 q0 = *reinterpret_cast<const float2*>(xr0 + cbase);
        float2 q1 = *reinterpret_cast<const float2*>(xr0 + cbase + 8);
        float2 q2 = *reinterpret_cast<const float2*>(xr1 + cbase);
        float2 q3 = *reinterpret_cast<const float2*>(xr1 + cbase + 8);

#pragma unroll 1
        for (int kt = 0; kt < 16; kt++) {
            float2 c0 = q0, c1 = q1, c2 = q2, c3 = q3;
            if (kt < 15) {
                int c = (kt + 1) * 16 + cbase;
                q0 = *reinterpret_cast<const float2*>(xr0 + c);
                q1 = *reinterpret_cast<const float2*>(xr0 + c + 8);
                q2 = *reinterpret_cast<const float2*>(xr1 + c);
                q3 = *reinterpret_cast<const float2*>(xr1 + c + 8);
            }
            // A fragments: a0=(r0,k0-7) a1=(r1,k0-7) a2=(r0,k8-15) a3=(r1,k8-15)
            uint32_t ah0 = pack_f16x2(c0.x, c0.y);
            uint32_t ah1 = pack_f16x2(c2.x, c2.y);
            uint32_t ah2 = pack_f16x2(c1.x, c1.y);
            uint32_t ah3 = pack_f16x2(c3.x, c3.y);

            // stage fp16(x) for the coalesced gmem write (pool pass input)
            {
                int col = kt * 8 + cb2;
                stage[g * STAGE_ROW + col]           = *reinterpret_cast<__half2*>(&ah0);
                stage[g * STAGE_ROW + col + 4]       = *reinterpret_cast<__half2*>(&ah2);
                stage[(g + 8) * STAGE_ROW + col]     = *reinterpret_cast<__half2*>(&ah1);
                stage[(g + 8) * STAGE_ROW + col + 4] = *reinterpret_cast<__half2*>(&ah3);
            }

            const uint4* bp = frag4 + kt * 256 + lane;
#pragma unroll
            for (int np = 0; np < 8; np++) {
                uint4 bb = bp[np * 32];             // one conflict-free LDS.128
                mma_f16(&acc[(2 * np    ) * 4], ah0, ah1, ah2, ah3, bb.x, bb.y);
                mma_f16(&acc[(2 * np + 1) * 4], ah0, ah1, ah2, ah3, bb.z, bb.w);
            }
        }

        // flush staged fp16 x tile: 16 rows x 512B, coalesced streaming STG.128
        __syncwarp();
        {
            __half2* dst = g_xf16 + (size_t)tile * 16 * (D_IN / 2);
#pragma unroll
            for (int r = 0; r < 16; r++) {
                uint4 v = *reinterpret_cast<const uint4*>(stage + r * STAGE_ROW + lane * 4);
                stg_cs_128(dst + (size_t)r * (D_IN / 2) + lane * 4, v);
            }
        }

        // epilogue: s = sum_n tanh(h + b1) * W2
        float p0 = 0.0f, p1 = 0.0f;
#pragma unroll
        for (int nt = 0; nt < 16; nt++) {
            int n0 = nt * 8 + cbase;
            float2 w0 = pw[n0];
            float2 w1 = pw[n0 + 1];
            p0 += fast_tanh(acc[nt * 4 + 0] + w0.x) * w0.y;
            p0 += fast_tanh(acc[nt * 4 + 1] + w1.x) * w1.y;
            p1 += fast_tanh(acc[nt * 4 + 2] + w0.x) * w0.y;
            p1 += fast_tanh(acc[nt * 4 + 3] + w1.x) * w1.y;
        }
        p0 += __shfl_xor_sync(0xffffffffu, p0, 1);
        p0 += __shfl_xor_sync(0xffffffffu, p0, 2);
        p1 += __shfl_xor_sync(0xffffffffu, p1, 1);
        p1 += __shfl_xor_sync(0xffffffffu, p1, 2);
        if ((lane & 3) == 0) {
            int r = tile * 16 + g;
            s_out[r]     = p0 + bias2;
            s_out[r + 8] = p1 + bias2;
        }
        __syncwarp();   // staged tile fully consumed before next iteration reuses it
    }
}

// ---------------------------------------------------------------------------
// Pass 2 (fused): per-segment softmax (in place) + weighted pooling.
// Block per segment, 256 threads.
//   phases 1-3: segment max, exp-sum (cached in smem), write attention weights
//   phase 4:    ctx[b,:] = sum w[n] * xf16[n,:]; 8 token-groups x 32 col-chunks
// ---------------------------------------------------------------------------
__global__ __launch_bounds__(256)
void softmax_pool_kernel(float* __restrict__ sw, float* __restrict__ ctx) {
    __shared__ float red[8];
    __shared__ float bc[2];
    __shared__ float ecache[POOL_CAP];
    __shared__ float sums[8][256];

    const int b   = blockIdx.x;
    const int s0  = g_start[b];
    const int s1  = g_start[b + 1];
    const int len = s1 - s0;
    const int tid = threadIdx.x;
    const bool cached = (len <= POOL_CAP);

    // ---- phase 1: segment max ----
    float m = -3.402823466e38f;
    for (int i = s0 + tid; i < s1; i += 256) m = fmaxf(m, sw[i]);
#pragma unroll
    for (int o = 16; o; o >>= 1) m = fmaxf(m, __shfl_xor_sync(0xffffffffu, m, o));
    if ((tid & 31) == 0) red[tid >> 5] = m;
    __syncthreads();
    if (tid == 0) {
        float v = red[0];
#pragma unroll
        for (int i = 1; i < 8; i++) v = fmaxf(v, red[i]);
        bc[0] = v;
    }
    __syncthreads();
    m = bc[0];

    // ---- phase 2: exp-sum (cache exp values) ----
    float sum = 0.0f;
    for (int i = s0 + tid; i < s1; i += 256) {
        float e = __expf(sw[i] - m);
        if (cached) ecache[i - s0] = e;
        sum += e;
    }
#pragma unroll
    for (int o = 16; o; o >>= 1) sum += __shfl_xor_sync(0xffffffffu, sum, o);
    __syncthreads();
    if ((tid & 31) == 0) red[tid >> 5] = sum;
    __syncthreads();
    if (tid == 0) {
        float v = 0.0f;
#pragma unroll
        for (int i = 0; i < 8; i++) v += red[i];
        bc[1] = v;
    }
    __syncthreads();
    const float inv = __fdividef(1.0f, bc[1]);

    // ---- phase 3: write attention weights; cache becomes w ----
    for (int i = s0 + tid; i < s1; i += 256) {
        float e = cached ? ecache[i - s0] : __expf(sw[i] - m);
        float wv = e * inv;
        sw[i] = wv;
        if (cached) ecache[i - s0] = wv;
    }
    __syncthreads();

    // ---- phase 4: pooling over fp16 x copy ----
    const int lane32 = tid & 31;      // 16B column chunk (8 features)
    const int grp    = tid >> 5;      // token group 0..7
    float acc[8];
#pragma unroll
    for (int j = 0; j < 8; j++) acc[j] = 0.0f;

    const uint4* xp = reinterpret_cast<const uint4*>(g_xf16) +
                      (size_t)(s0 + grp) * 32 + lane32;
    for (int tok = s0 + grp; tok < s1; tok += 8) {
        float wv = cached ? ecache[tok - s0] : __ldcg(sw + tok);
        uint4 v = __ldg(xp);
        xp += 8 * 32;
        float2 f0 = __half22float2(*reinterpret_cast<const __half2*>(&v.x));
        float2 f1 = __half22float2(*reinterpret_cast<const __half2*>(&v.y));
        float2 f2 = __half22float2(*reinterpret_cast<const __half2*>(&v.z));
        float2 f3 = __half22float2(*reinterpret_cast<const __half2*>(&v.w));
        acc[0] += wv * f0.x;  acc[1] += wv * f0.y;
        acc[2] += wv * f1.x;  acc[3] += wv * f1.y;
        acc[4] += wv * f2.x;  acc[5] += wv * f2.y;
        acc[6] += wv * f3.x;  acc[7] += wv * f3.y;
    }
#pragma unroll
    for (int j = 0; j < 8; j++) sums[grp][lane32 * 8 + j] = acc[j];
    __syncthreads();
    float r = 0.0f;
#pragma unroll
    for (int gi = 0; gi < 8; gi++) r += sums[gi][tid];
    ctx[(size_t)b * D_IN + tid] = r;
}

// ---------------------------------------------------------------------------
// launch: outputs are [context_vectors (B*D)] then [attention_weights (N)]
// ---------------------------------------------------------------------------
extern "C" void kernel_launch(void* const* d_in, const int* in_sizes, int n_in,
                              void* d_out, int out_size) {
    const float* x   = (const float*)d_in[0];
    const int*   seg = (const int*)d_in[1];
    const float* W1  = (const float*)d_in[2];
    const float* b1  = (const float*)d_in[3];
    const float* W2  = (const float*)d_in[4];
    const float* b2  = (const float*)d_in[5];

    float* ctx = (float*)d_out;                       // [B, D]
    float* sw  = ctx + (size_t)B_SEG * D_IN;          // [N] : logits then weights

    cudaFuncSetAttribute(logits_kernel,
                         cudaFuncAttributeMaxDynamicSharedMemorySize, SMEM_LG);

    find_starts_kernel<<<(B_SEG + 256) / 256, 256>>>(seg);
    logits_kernel<<<GRID_LG, 512, SMEM_LG>>>(x, W1, b1, W2, b2, sw);
    softmax_pool_kernel<<<B_SEG, 256>>>(sw, ctx);
}

// round 14
// speedup vs baseline: 1.9181x; 1.2692x over previous
#include <cuda_runtime.h>
#include <cuda_fp16.h>
#include <cstdint>
#include <cstddef>

// Problem constants (fixed by the dataset)
#define N_TOK   1048576
#define B_SEG   4096
#define D_IN    256
#define H_MLP   128
#define N_TILES (N_TOK / 16)      // 65536 tiles of 16 tokens
#define GRID_LG 152

// smem layout for logits kernel
//  [0, 65536)        : W1 fp16 B-fragments, uint4 x (16 kt * 8 np * 32 ln)
//  [65536, 66560)    : 128 x float2 {b1, W2}
//  [66560, 201728)   : per-warp staging for fp16(x): 16 warps x 16 rows x 132 half2
#define FRAG4_ELEMS (16 * 8 * 32)
#define SM_PW       (FRAG4_ELEMS * 16)
#define SM_STAGE    (SM_PW + H_MLP * 8)
#define STAGE_ROW   132                       // 128 data half2 + 4 pad
#define STAGE_WARP  (16 * STAGE_ROW)
#define SMEM_LG     (SM_STAGE + 16 * STAGE_WARP * 4)

__device__ float g_denom[B_SEG];

// ---------------------------------------------------------------------------
// helpers
// ---------------------------------------------------------------------------
__device__ __forceinline__ uint32_t pack_f16x2(float lo, float hi) {
    // lower 16 bits = fp16(lo), upper = fp16(hi)
    uint32_t r;
    asm("cvt.rn.f16x2.f32 %0, %1, %2;" : "=r"(r) : "f"(hi), "f"(lo));
    return r;
}

__device__ __forceinline__ void mma_f16(float d[4],
                                        uint32_t a0, uint32_t a1, uint32_t a2, uint32_t a3,
                                        uint32_t b0, uint32_t b1) {
    asm volatile(
        "mma.sync.aligned.m16n8k16.row.col.f32.f16.f16.f32 "
        "{%0,%1,%2,%3}, {%4,%5,%6,%7}, {%8,%9}, {%0,%1,%2,%3};\n"
        : "+f"(d[0]), "+f"(d[1]), "+f"(d[2]), "+f"(d[3])
        : "r"(a0), "r"(a1), "r"(a2), "r"(a3), "r"(b0), "r"(b1));
}

__device__ __forceinline__ float fast_tanh(float v) {
    float e = __expf(2.0f * v);
    return 1.0f - __fdividef(2.0f, e + 1.0f);
}

// ---------------------------------------------------------------------------
// Pass 0: zero the atomic accumulation targets (ctx region of d_out + denom).
// d_out is poisoned 0xAA before timing, so every launch must re-zero.
// ---------------------------------------------------------------------------
__global__ void zero_kernel(float* __restrict__ ctx) {
    int i = blockIdx.x * blockDim.x + threadIdx.x;
    if (i < B_SEG * D_IN) ctx[i] = 0.0f;
    if (i < B_SEG) g_denom[i] = 0.0f;
}

// ---------------------------------------------------------------------------
// Pass 1 (fused): per 16-token warp tile
//   s  = tanh(x @ W1 + b1) @ W2 + b2      (single fp16 MMA GEMM)
//   z  = exp(s)                            -> written to sw (normalized later)
//   atomically accumulate ctx[seg] += z * fp16(x),  denom[seg] += z
// exp without max-subtraction is safe: |s| <= sum|W2| ~= 9  =>  z <= ~8100.
// ---------------------------------------------------------------------------
__global__ __launch_bounds__(512, 1)
void logits_pool_kernel(const float* __restrict__ x,
                        const int* __restrict__ seg,
                        const float* __restrict__ W1,
                        const float* __restrict__ b1,
                        const float* __restrict__ W2,
                        const float* __restrict__ b2,
                        float* __restrict__ sw,
                        float* __restrict__ ctx) {
    extern __shared__ unsigned char smem_raw[];
    uint4*  frag4 = reinterpret_cast<uint4*>(smem_raw);
    float2* pw    = reinterpret_cast<float2*>(smem_raw + SM_PW);

    const int tid = threadIdx.x;

    // --- pack W1 (fp16) into paired B-fragment layout: uint4 = {nt=2np, nt=2np+1} ---
    for (int e = tid; e < FRAG4_ELEMS; e += 512) {
        int kt = e >> 8;              // 0..15
        int np = (e >> 5) & 7;        // 0..7 (nt pair)
        int ln = e & 31;
        int k0 = kt * 16 + (ln & 3) * 2;
        int nn = np * 16 + (ln >> 2);       // column for nt = 2np
        float v0 = W1[(k0    ) * H_MLP + nn];
        float v1 = W1[(k0 + 1) * H_MLP + nn];
        float v2 = W1[(k0 + 8) * H_MLP + nn];
        float v3 = W1[(k0 + 9) * H_MLP + nn];
        float u0 = W1[(k0    ) * H_MLP + nn + 8];
        float u1 = W1[(k0 + 1) * H_MLP + nn + 8];
        float u2 = W1[(k0 + 8) * H_MLP + nn + 8];
        float u3 = W1[(k0 + 9) * H_MLP + nn + 8];
        frag4[e] = make_uint4(pack_f16x2(v0, v1), pack_f16x2(v2, v3),
                              pack_f16x2(u0, u1), pack_f16x2(u2, u3));
    }
    for (int n = tid; n < H_MLP; n += 512)
        pw[n] = make_float2(b1[n], W2[n]);
    const float bias2 = b2[0];
    __syncthreads();

    const int warp  = tid >> 5;
    const int lane  = tid & 31;
    const int g     = lane >> 2;          // row within 8-row groups
    const int cbase = (lane & 3) * 2;     // col pair base
    const int cb2   = lane & 3;           // half2 column index within 8

    __half2* stage = reinterpret_cast<__half2*>(smem_raw + SM_STAGE) + warp * STAGE_WARP;

    for (int tile = blockIdx.x * 16 + warp; tile < N_TILES; tile += GRID_LG * 16) {
        const float* xr0 = x + (size_t)(tile * 16 + g) * D_IN;
        const float* xr1 = xr0 + 8 * D_IN;

        // segment ids for this tile's 16 tokens (broadcast later via shfl)
        int sgid = 0;
        if (lane < 16) sgid = seg[tile * 16 + lane];

        float acc[64];
#pragma unroll
        for (int i = 0; i < 64; i++) acc[i] = 0.0f;

        // prefetch kt = 0
        float2 q0 = *reinterpret_cast<const float2*>(xr0 + cbase);
        float2 q1 = *reinterpret_cast<const float2*>(xr0 + cbase + 8);
        float2 q2 = *reinterpret_cast<const float2*>(xr1 + cbase);
        float2 q3 = *reinterpret_cast<const float2*>(xr1 + cbase + 8);

#pragma unroll 1
        for (int kt = 0; kt < 16; kt++) {
            float2 c0 = q0, c1 = q1, c2 = q2, c3 = q3;
            if (kt < 15) {
                int c = (kt + 1) * 16 + cbase;
                q0 = *reinterpret_cast<const float2*>(xr0 + c);
                q1 = *reinterpret_cast<const float2*>(xr0 + c + 8);
                q2 = *reinterpret_cast<const float2*>(xr1 + c);
                q3 = *reinterpret_cast<const float2*>(xr1 + c + 8);
            }
            // A fragments: a0=(r0,k0-7) a1=(r1,k0-7) a2=(r0,k8-15) a3=(r1,k8-15)
            uint32_t ah0 = pack_f16x2(c0.x, c0.y);
            uint32_t ah1 = pack_f16x2(c2.x, c2.y);
            uint32_t ah2 = pack_f16x2(c1.x, c1.y);
            uint32_t ah3 = pack_f16x2(c3.x, c3.y);

            // stage fp16(x) for the fused pooling phase
            {
                int col = kt * 8 + cb2;
                stage[g * STAGE_ROW + col]           = *reinterpret_cast<__half2*>(&ah0);
                stage[g * STAGE_ROW + col + 4]       = *reinterpret_cast<__half2*>(&ah2);
                stage[(g + 8) * STAGE_ROW + col]     = *reinterpret_cast<__half2*>(&ah1);
                stage[(g + 8) * STAGE_ROW + col + 4] = *reinterpret_cast<__half2*>(&ah3);
            }

            const uint4* bp = frag4 + kt * 256 + lane;
#pragma unroll
            for (int np = 0; np < 8; np++) {
                uint4 bb = bp[np * 32];             // one conflict-free LDS.128
                mma_f16(&acc[(2 * np    ) * 4], ah0, ah1, ah2, ah3, bb.x, bb.y);
                mma_f16(&acc[(2 * np + 1) * 4], ah0, ah1, ah2, ah3, bb.z, bb.w);
            }
        }

        // epilogue: s = sum_n tanh(h + b1) * W2  ->  z = exp(s + b2)
        float p0 = 0.0f, p1 = 0.0f;
#pragma unroll
        for (int nt = 0; nt < 16; nt++) {
            int n0 = nt * 8 + cbase;
            float2 w0 = pw[n0];
            float2 w1 = pw[n0 + 1];
            p0 += fast_tanh(acc[nt * 4 + 0] + w0.x) * w0.y;
            p0 += fast_tanh(acc[nt * 4 + 1] + w1.x) * w1.y;
            p1 += fast_tanh(acc[nt * 4 + 2] + w0.x) * w0.y;
            p1 += fast_tanh(acc[nt * 4 + 3] + w1.x) * w1.y;
        }
        p0 += __shfl_xor_sync(0xffffffffu, p0, 1);
        p0 += __shfl_xor_sync(0xffffffffu, p0, 2);
        p1 += __shfl_xor_sync(0xffffffffu, p1, 1);
        p1 += __shfl_xor_sync(0xffffffffu, p1, 2);

        const float z0 = __expf(p0 + bias2);        // row g
        const float z1 = __expf(p1 + bias2);        // row g + 8
        if ((lane & 3) == 0) {
            int r = tile * 16 + g;
            sw[r]     = z0;
            sw[r + 8] = z1;
        }
        __syncwarp();   // stage fully written by all lanes before cross-lane reads

        // ---- fused pooling: ctx[sid] += z * x_fp16, denom[sid] += z ----
        // lane handles smem columns c = lane + 32j (j=0..3) -> features f(c), f(c)+1
        {
            float facc[8];
#pragma unroll
            for (int j = 0; j < 8; j++) facc[j] = 0.0f;
            float zsum = 0.0f;
            int cur = __shfl_sync(0xffffffffu, sgid, 0);

#pragma unroll 1
            for (int tok = 0; tok < 16; tok++) {
                int sid_t = __shfl_sync(0xffffffffu, sgid, tok);
                float zt = (tok < 8)
                    ? __shfl_sync(0xffffffffu, z0, tok * 4)
                    : __shfl_sync(0xffffffffu, z1, (tok - 8) * 4);
                if (sid_t != cur) {
                    // flush previous segment group
#pragma unroll
                    for (int j = 0; j < 4; j++) {
                        int c = lane + 32 * j;
                        int f = 16 * (c >> 3) + ((c & 4) << 1) + ((c & 3) << 1);
                        atomicAdd(ctx + (size_t)cur * D_IN + f,     facc[2 * j]);
                        atomicAdd(ctx + (size_t)cur * D_IN + f + 1, facc[2 * j + 1]);
                        facc[2 * j] = 0.0f; facc[2 * j + 1] = 0.0f;
                    }
                    if (lane == 0) atomicAdd(&g_denom[cur], zsum);
                    zsum = 0.0f;
                    cur = sid_t;
                }
                zsum += zt;
#pragma unroll
                for (int j = 0; j < 4; j++) {
                    __half2 hv = stage[tok * STAGE_ROW + lane + 32 * j];
                    float2 fv = __half22float2(hv);
                    facc[2 * j]     += zt * fv.x;
                    facc[2 * j + 1] += zt * fv.y;
                }
            }
            // final flush
#pragma unroll
            for (int j = 0; j < 4; j++) {
                int c = lane + 32 * j;
                int f = 16 * (c >> 3) + ((c & 4) << 1) + ((c & 3) << 1);
                atomicAdd(ctx + (size_t)cur * D_IN + f,     facc[2 * j]);
                atomicAdd(ctx + (size_t)cur * D_IN + f + 1, facc[2 * j + 1]);
            }
            if (lane == 0) atomicAdd(&g_denom[cur], zsum);
        }
        __syncwarp();   // stage fully consumed before next iteration overwrites
    }
}

// ---------------------------------------------------------------------------
// Pass 2a: attention_weights[i] = z[i] / denom[seg[i]]
// ---------------------------------------------------------------------------
__global__ __launch_bounds__(256)
void norm_w_kernel(float* __restrict__ sw, const int* __restrict__ seg) {
    int i = blockIdx.x * blockDim.x + threadIdx.x;
    if (i >= N_TOK) return;
    float d = __ldg(&g_denom[__ldg(seg + i)]);
    sw[i] = sw[i] / d;
}

// ---------------------------------------------------------------------------
// Pass 2b: ctx[b,:] /= denom[b]   (empty segment -> 0, matching segment_sum)
// ---------------------------------------------------------------------------
__global__ __launch_bounds__(256)
void norm_ctx_kernel(float* __restrict__ ctx) {
    int i = blockIdx.x * blockDim.x + threadIdx.x;
    if (i >= B_SEG * D_IN) return;
    float d = g_denom[i >> 8];
    float v = ctx[i];
    ctx[i] = (d > 0.0f) ? v / d : 0.0f;
}

// ---------------------------------------------------------------------------
// launch: outputs are [context_vectors (B*D)] then [attention_weights (N)]
// ---------------------------------------------------------------------------
extern "C" void kernel_launch(void* const* d_in, const int* in_sizes, int n_in,
                              void* d_out, int out_size) {
    const float* x   = (const float*)d_in[0];
    const int*   seg = (const int*)d_in[1];
    const float* W1  = (const float*)d_in[2];
    const float* b1  = (const float*)d_in[3];
    const float* W2  = (const float*)d_in[4];
    const float* b2  = (const float*)d_in[5];

    float* ctx = (float*)d_out;                       // [B, D]
    float* sw  = ctx + (size_t)B_SEG * D_IN;          // [N] : z then weights

    cudaFuncSetAttribute(logits_pool_kernel,
                         cudaFuncAttributeMaxDynamicSharedMemorySize, SMEM_LG);

    zero_kernel<<<(B_SEG * D_IN + 511) / 512, 512>>>(ctx);
    logits_pool_kernel<<<GRID_LG, 512, SMEM_LG>>>(x, seg, W1, b1, W2, b2, sw, ctx);
    norm_w_kernel<<<N_TOK / 256, 256>>>(sw, seg);
    norm_ctx_kernel<<<(B_SEG * D_IN) / 256, 256>>>(ctx);
}